// round 14
// baseline (speedup 1.0000x reference)
#include <cuda_runtime.h>
#include <cuda_bf16.h>
#include <cuda_fp16.h>
#include <math.h>
#include <cstdint>

// Problem constants
#define BB   128
#define SS   1024
#define DIN  1024
#define NQ   8
#define NB   256
#define NH   4
#define TOKN (BB*SS)           // 131072 tokens
#define UOFF ((size_t)TOKN*NB) // offset of uncertainty in d_out

// Scratch (device globals: allocation-free)
__device__ float g_real[TOKN*NQ];
__device__ float g_imag[TOKN*NQ];
__device__ float g_meas[TOKN*NQ];
// fp16 unc_w image for mma.sync (2-product split: only W_hi needed):
// slab k64 = 0..3, each 32 KB = [256 o][64 k] fp16, ldmatrix-swizzled (128B rows).
__device__ unsigned char g_wimg[4*32768];
// Packed (amp,phase) projection weights: g_wax[k*8+j] = (aw[j][k], pw[j][k])
__device__ unsigned long long g_wax[DIN*8];

// ---------- f32x2 packed-FMA helpers ----------
static __device__ __forceinline__ unsigned long long pk2(float lo, float hi) {
    unsigned long long r;
    asm("mov.b64 %0, {%1,%2};" : "=l"(r) : "f"(lo), "f"(hi));
    return r;
}
static __device__ __forceinline__ void upk2(unsigned long long v, float& lo, float& hi) {
    asm("mov.b64 {%0,%1}, %2;" : "=f"(lo), "=f"(hi) : "l"(v));
}
static __device__ __forceinline__ unsigned long long ffma2(unsigned long long a,
                                                           unsigned long long b,
                                                           unsigned long long c) {
    unsigned long long d;
    asm("fma.rn.f32x2 %0, %1, %2, %3;" : "=l"(d) : "l"(a), "l"(b), "l"(c));
    return d;
}
static __device__ __forceinline__ float ex2f(float x) {
    float r;
    asm("ex2.approx.f32 %0, %1;" : "=f"(r) : "f"(x));
    return r;
}

// ---------- mma.sync / cp.async helpers (base-target) ----------
static __device__ __forceinline__ uint32_t smem_u32(const void* p) {
    uint32_t a;
    asm("{ .reg .u64 t; cvta.to.shared.u64 t, %1; cvt.u32.u64 %0, t; }" : "=r"(a) : "l"(p));
    return a;
}
#define LDSM4(r, addr) \
    asm volatile("ldmatrix.sync.aligned.m8n8.x4.shared.b16 {%0,%1,%2,%3}, [%4];" \
        : "=r"((r)[0]), "=r"((r)[1]), "=r"((r)[2]), "=r"((r)[3]) : "r"(addr))
#define MMA16816H(d, a, b0v, b1v) \
    asm volatile("mma.sync.aligned.m16n8k16.row.col.f32.f16.f16.f32 " \
        "{%0,%1,%2,%3}, {%4,%5,%6,%7}, {%8,%9}, {%0,%1,%2,%3};" \
        : "+f"((d)[0]), "+f"((d)[1]), "+f"((d)[2]), "+f"((d)[3]) \
        : "r"((a)[0]), "r"((a)[1]), "r"((a)[2]), "r"((a)[3]), "r"(b0v), "r"(b1v))
#define CP_ASYNC16(dst, src) \
    asm volatile("cp.async.cg.shared.global [%0], [%1], 16;" :: "r"(dst), "l"(src))
#define CP_COMMIT() asm volatile("cp.async.commit_group;" ::: "memory")
#define CP_WAIT(n)  asm volatile("cp.async.wait_group %0;" :: "n"(n) : "memory")

// ---------- prep: unc_w -> fp16 slabs [256 o][64 k] ----------
__global__ void kTW(const float* __restrict__ unc_w) {
    int idx = blockIdx.x * blockDim.x + threadIdx.x;
    if (idx >= NB*NB) return;
    int o = idx >> 8, k = idx & 255;
    float w = unc_w[o*NB + k];
    int k64 = k >> 6, kk = k & 63;
    unsigned byte = (unsigned)(o*128 + kk*2);
    byte ^= (o & 7) << 4;                       // ldmatrix swizzle (128B rows)
    *(__half*)(g_wimg + (size_t)k64*32768 + byte) = __float2half_rn(w);
}

// ---------- prep: pack (amp,phase) projection weights ----------
__global__ void kTA(const float* __restrict__ aw, const float* __restrict__ pw) {
    int idx = blockIdx.x * blockDim.x + threadIdx.x;
    if (idx >= DIN*8) return;
    int k = idx >> 3, j = idx & 7;
    g_wax[k*8 + j] = pk2(aw[j*DIN + k], pw[j*DIN + k]);
}

// ---------- Stage A: coalesced smem-staged projections + activations ----------
#define KCH 32
__global__ void __launch_bounds__(256) kA(const float* __restrict__ x,
                                          const float* __restrict__ ab,
                                          const float* __restrict__ pb) {
    __shared__ float4 tile[2][2048];            // 2 x 32 KB
    __shared__ unsigned long long wch[2][256];  // 2 x 2 KB
    const int tid = threadIdx.x;
    const size_t T0 = (size_t)blockIdx.x * 256;
    const uint32_t sb_tile = smem_u32(&tile[0][0]);
    const uint32_t sb_w    = smem_u32(&wch[0][0]);

#pragma unroll
    for (int pc = 0; pc < 2; pc++) {
#pragma unroll
        for (int i = 0; i < 8; i++) {
            int idx = i*256 + tid;
            int t = idx >> 3, k4 = idx & 7;
            const char* src = (const char*)(x + (T0 + t)*DIN + pc*KCH) + k4*16;
            uint32_t dst = sb_tile + pc*32768 + t*128 + ((k4 ^ (t & 7)) * 16);
            CP_ASYNC16(dst, src);
        }
        if (tid < 128)
            CP_ASYNC16(sb_w + pc*2048 + tid*16,
                       (const char*)g_wax + pc*2048 + tid*16);
        CP_COMMIT();
    }

    unsigned long long acc[8];
#pragma unroll
    for (int j = 0; j < 8; j++) acc[j] = 0ull;

#pragma unroll 1
    for (int c = 0; c < 32; c++) {
        const int buf = c & 1;
        if (c < 31) { CP_WAIT(1); } else { CP_WAIT(0); }
        __syncthreads();

        float4 xr[8];
#pragma unroll
        for (int k4 = 0; k4 < 8; k4++)
            xr[k4] = tile[buf][tid*8 + (k4 ^ (tid & 7))];

        const unsigned long long* wj = wch[buf];
#pragma unroll
        for (int kk = 0; kk < 32; kk++) {
            float xv = ((const float*)&xr[kk >> 2])[kk & 3];
            unsigned long long xp = pk2(xv, xv);
            const ulonglong2* wp = (const ulonglong2*)(wj + kk*8);
            ulonglong2 w01 = wp[0], w23 = wp[1], w45 = wp[2], w67 = wp[3];
            acc[0] = ffma2(xp, w01.x, acc[0]);
            acc[1] = ffma2(xp, w01.y, acc[1]);
            acc[2] = ffma2(xp, w23.x, acc[2]);
            acc[3] = ffma2(xp, w23.y, acc[3]);
            acc[4] = ffma2(xp, w45.x, acc[4]);
            acc[5] = ffma2(xp, w45.y, acc[5]);
            acc[6] = ffma2(xp, w67.x, acc[6]);
            acc[7] = ffma2(xp, w67.y, acc[7]);
        }
        __syncthreads();

        if (c + 2 < 32) {
#pragma unroll
            for (int i = 0; i < 8; i++) {
                int idx = i*256 + tid;
                int t = idx >> 3, k4 = idx & 7;
                const char* src = (const char*)(x + (T0 + t)*DIN + (c+2)*KCH) + k4*16;
                uint32_t dst = sb_tile + buf*32768 + t*128 + ((k4 ^ (t & 7)) * 16);
                CP_ASYNC16(dst, src);
            }
            if (tid < 128)
                CP_ASYNC16(sb_w + buf*2048 + tid*16,
                           (const char*)g_wax + (c+2)*2048 + tid*16);
            CP_COMMIT();
        }
    }

    float orr[8], oii[8];
#pragma unroll
    for (int j = 0; j < 8; j++) {
        float va, vp;
        upk2(acc[j], va, vp);
        float amp = tanhf(va + __ldg(ab + j));
        float ph  = 6.283185307179586f / (1.0f + expf(-(vp + __ldg(pb + j))));
        float s, cc;
        sincosf(ph, &s, &cc);
        orr[j] = amp * cc;
        oii[j] = amp * s;
    }
    float4* pr = (float4*)(g_real + (T0 + tid)*NQ);
    float4* pi = (float4*)(g_imag + (T0 + tid)*NQ);
    pr[0] = make_float4(orr[0], orr[1], orr[2], orr[3]);
    pr[1] = make_float4(orr[4], orr[5], orr[6], orr[7]);
    pi[0] = make_float4(oii[0], oii[1], oii[2], oii[3]);
    pi[1] = make_float4(oii[4], oii[5], oii[6], oii[7]);
}

// ---------- Stage B: dual MHA + out_proj + |.| (packed, ex2-based softmax) ----------
// q pre-scaled by (1/sqrt(Dh))*log2(e) so the score IS the ex2 argument.
__global__ void __launch_bounds__(128) kB(const float* __restrict__ ipw,
                                          const float* __restrict__ ipb,
                                          const float* __restrict__ opw,
                                          const float* __restrict__ opb) {
    __shared__ float4 ksv[128][4];
    __shared__ float4 vsv[128][4];
    __shared__ float s_ipw[24][8];
    __shared__ float s_ipb[24];
    __shared__ float s_opw[8][8];
    __shared__ float s_opb[8];

    const int l = threadIdx.x;
    const int n = blockIdx.x;

    if (l < 24) {
        s_ipb[l] = ipb[l];
#pragma unroll
        for (int e = 0; e < 8; e++) s_ipw[l][e] = ipw[l*8 + e];
    }
    if (l < 8) {
        s_opb[l] = opb[l];
#pragma unroll
        for (int j = 0; j < 8; j++) s_opw[l][j] = opw[l*8 + j];
    }

    const size_t base = ((size_t)l * SS + n) * NQ;
    float st[2][8];
    {
        float4 r0 = *(const float4*)(g_real + base);
        float4 r1 = *(const float4*)(g_real + base + 4);
        float4 i0 = *(const float4*)(g_imag + base);
        float4 i1 = *(const float4*)(g_imag + base + 4);
        st[0][0]=r0.x; st[0][1]=r0.y; st[0][2]=r0.z; st[0][3]=r0.w;
        st[0][4]=r1.x; st[0][5]=r1.y; st[0][6]=r1.z; st[0][7]=r1.w;
        st[1][0]=i0.x; st[1][1]=i0.y; st[1][2]=i0.z; st[1][3]=i0.w;
        st[1][4]=i1.x; st[1][5]=i1.y; st[1][6]=i1.z; st[1][7]=i1.w;
    }
    __syncthreads();

    float qb[2][8];
    float kv0[8], kv1[8], vv0[8], vv1[8];
#pragma unroll
    for (int p = 0; p < 2; p++) {
#pragma unroll
        for (int j = 0; j < 8; j++) {
            float q = s_ipb[j], k = s_ipb[8+j], v = s_ipb[16+j];
#pragma unroll
            for (int e = 0; e < 8; e++) {
                q = fmaf(s_ipw[j][e],    st[p][e], q);
                k = fmaf(s_ipw[8+j][e],  st[p][e], k);
                v = fmaf(s_ipw[16+j][e], st[p][e], v);
            }
            qb[p][j] = q;
            if (p == 0) { kv0[j] = k; vv0[j] = v; }
            else        { kv1[j] = k; vv1[j] = v; }
        }
    }
#pragma unroll
    for (int h = 0; h < NH; h++) {
        ksv[l][h] = make_float4(kv0[2*h], kv1[2*h], kv0[2*h+1], kv1[2*h+1]);
        vsv[l][h] = make_float4(vv0[2*h], vv1[2*h], vv0[2*h+1], vv1[2*h+1]);
    }
    __syncthreads();

    // packed q per head, pre-scaled by (1/sqrt(2))*log2(e)
    const float SC = 0.70710678118654752f * 1.4426950408889634f;
    unsigned long long qp0[NH], qp1[NH];
#pragma unroll
    for (int h = 0; h < NH; h++) {
        qp0[h] = pk2(qb[0][2*h]*SC,   qb[1][2*h]*SC);
        qp1[h] = pk2(qb[0][2*h+1]*SC, qb[1][2*h+1]*SC);
    }
    const unsigned long long one2 = pk2(1.0f, 1.0f);

    unsigned long long den2[NH], o02[NH], o12[NH];
#pragma unroll
    for (int h = 0; h < NH; h++) { den2[h] = 0ull; o02[h] = 0ull; o12[h] = 0ull; }

    for (int m = 0; m < 128; m++) {
        const ulonglong2* kr = (const ulonglong2*)&ksv[m][0];
        const ulonglong2* vr = (const ulonglong2*)&vsv[m][0];
#pragma unroll
        for (int h = 0; h < NH; h++) {
            ulonglong2 kk = kr[h];
            ulonglong2 vv = vr[h];
            unsigned long long s2 = ffma2(qp1[h], kk.y, 0ull);
            s2 = ffma2(qp0[h], kk.x, s2);
            float s0, s1;
            upk2(s2, s0, s1);
            unsigned long long e2 = pk2(ex2f(s0), ex2f(s1));
            den2[h] = ffma2(e2, one2, den2[h]);
            o02[h]  = ffma2(e2, vv.x, o02[h]);
            o12[h]  = ffma2(e2, vv.y, o12[h]);
        }
    }

    float ent[2][8];
#pragma unroll
    for (int h = 0; h < NH; h++) {
        float d0, d1, a0, a1, b0, b1;
        upk2(den2[h], d0, d1);
        upk2(o02[h], a0, a1);
        upk2(o12[h], b0, b1);
        float i0 = __fdividef(1.0f, d0), i1 = __fdividef(1.0f, d1);
        ent[0][2*h]   = a0 * i0;  ent[1][2*h]   = a1 * i1;
        ent[0][2*h+1] = b0 * i0;  ent[1][2*h+1] = b1 * i1;
    }

    float out[8];
#pragma unroll
    for (int e = 0; e < 8; e++) {
        float er = s_opb[e], ei = s_opb[e];
#pragma unroll
        for (int j = 0; j < 8; j++) {
            er = fmaf(s_opw[e][j], ent[0][j], er);
            ei = fmaf(s_opw[e][j], ent[1][j], ei);
        }
        out[e] = sqrtf(er*er + ei*ei);
    }
    float4* pm = (float4*)(g_meas + base);
    pm[0] = make_float4(out[0], out[1], out[2], out[3]);
    pm[1] = make_float4(out[4], out[5], out[6], out[7]);
}

// ---------- Stage C: fused compressed + fp16 2-product mma.sync GEMM ----------
// CTA = 128 tokens x 256 outputs, 512 threads. A = Ah + Al (fp16 pair, ~22
// bits of the fp32 compressed value); W = Wh (fp16). out = Ah*Wh + Al*Wh.
// 4 W slabs [256 o][64 k], cp.async double-buffered, prefetch 2 ahead.
#define OFF_MEAS 0
#define OFF_BIAS 4096
#define OFF_A    5120
#define OFF_ALO  (OFF_A + 65536)
#define OFF_W0   (OFF_ALO + 65536)
#define OFF_W1   (OFF_W0 + 32768)
#define SMEM_TOT (OFF_W1 + 32768)   // 201728 bytes

__global__ void __launch_bounds__(512, 1) kCm(const float* __restrict__ meas_w,
                                              const float* __restrict__ meas_b,
                                              const float* __restrict__ unc_b,
                                              float* __restrict__ out) {
    extern __shared__ unsigned char sm[];
    const uint32_t sb = smem_u32(sm);
    const int tid = threadIdx.x, wid = tid >> 5, lane = tid & 31;
    const size_t T0 = (size_t)blockIdx.x * 128;

    // Prologue: prefetch W slabs 0/1 (overlaps phase 1).
    {
        const char* src0 = (const char*)g_wimg + (size_t)tid*16;
        uint32_t d0 = sb + OFF_W0 + tid*16;
        uint32_t d1 = sb + OFF_W1 + tid*16;
#pragma unroll
        for (int i = 0; i < 4; i++) CP_ASYNC16(d0 + i*8192, src0 + i*8192);
        CP_COMMIT();
#pragma unroll
        for (int i = 0; i < 4; i++) CP_ASYNC16(d1 + i*8192, src0 + 32768 + i*8192);
        CP_COMMIT();
    }

    if (tid < 256) {
        ((float4*)(sm + OFF_MEAS))[tid] = __ldg((const float4*)(g_meas + T0*NQ) + tid);
        ((float*)(sm + OFF_BIAS))[tid] = __ldg(unc_b + tid);
    }
    __syncthreads();

    // ---- Phase 1: compressed + fp16 split into swizzled A tiles ----
    {
        const int o  = tid & 255;
        const int th = tid >> 8;
        float4 w0 = __ldg((const float4*)(meas_w + o*NQ));
        float4 w1 = __ldg((const float4*)(meas_w + o*NQ) + 1);
        float bb  = __ldg(meas_b + o);
        float* orow = out + T0*NB + o;
        const int tbase = th*64;
#pragma unroll 4
        for (int tt = 0; tt < 64; tt++) {
            const int t = tbase + tt;
            const float4* mm = (const float4*)(sm + OFF_MEAS + t*32);
            float4 m0 = mm[0], m1 = mm[1];
            float cc = bb;
            cc = fmaf(w0.x, m0.x, cc); cc = fmaf(w0.y, m0.y, cc);
            cc = fmaf(w0.z, m0.z, cc); cc = fmaf(w0.w, m0.w, cc);
            cc = fmaf(w1.x, m1.x, cc); cc = fmaf(w1.y, m1.y, cc);
            cc = fmaf(w1.z, m1.z, cc); cc = fmaf(w1.w, m1.w, cc);
            orow[(size_t)t*NB] = cc;
            __half hi = __float2half_rn(cc);
            __half lo = __float2half_rn(cc - __half2float(hi));
            unsigned byte = (unsigned)(t*512 + o*2);
            byte ^= (t & 7) << 4;                 // ldmatrix swizzle (512B rows)
            *(__half*)(sm + OFF_A   + byte) = hi;
            *(__half*)(sm + OFF_ALO + byte) = lo;
        }
    }

    // ---- Phase 2: 4-slab pipelined loop, both output halves accumulated ----
    const int mg = wid & 3;    // token group: rows mg*32..+32
    const int ng = wid >> 2;   // 32-col group within each 128-col half
    const unsigned a_m   = (unsigned)(mg*32 + (lane & 15));
    const unsigned a_k8  = (unsigned)((lane >> 4) << 3);
    const unsigned b_lrow = (unsigned)((lane & 7) + ((lane >> 4) << 3));
    const unsigned b_k8  = (unsigned)(((lane >> 3) & 1) << 3);

    float acc[64];
#pragma unroll
    for (int i = 0; i < 64; i++) acc[i] = 0.f;

#pragma unroll 1
    for (int q = 0; q < 4; q++) {
        const uint32_t wbase = sb + ((q & 1) ? OFF_W1 : OFF_W0);

        if (q < 3) { CP_WAIT(1); } else { CP_WAIT(0); }
        __syncthreads();

#pragma unroll
        for (int s = 0; s < 4; s++) {
            uint32_t ah[2][4], al[2][4], b[8][2];
#pragma unroll
            for (int mt = 0; mt < 2; mt++) {
                unsigned m = a_m + mt*16;
                unsigned k = (unsigned)(q*64 + s*16) + a_k8;
                unsigned byte = (m*512 + k*2) ^ ((m & 7) << 4);
                LDSM4(ah[mt], sb + OFF_A   + byte);
                LDSM4(al[mt], sb + OFF_ALO + byte);
            }
#pragma unroll
            for (int np = 0; np < 4; np++) {
                unsigned row = (np < 2 ? (unsigned)(ng*32 + np*16)
                                       : (unsigned)(128 + ng*32 + (np-2)*16)) + b_lrow;
                unsigned kin = (unsigned)(s*16) + b_k8;
                unsigned byte = (row*128 + kin*2) ^ ((row & 7) << 4);
                uint32_t r[4];
                LDSM4(r, wbase + byte);
                b[np*2][0]   = r[0];  b[np*2][1]   = r[1];
                b[np*2+1][0] = r[2];  b[np*2+1][1] = r[3];
            }
#pragma unroll
            for (int mt = 0; mt < 2; mt++) {
#pragma unroll
                for (int nt = 0; nt < 8; nt++) {
                    float* d = &acc[(mt*8 + nt)*4];
                    MMA16816H(d, ah[mt], b[nt][0], b[nt][1]);
                    MMA16816H(d, al[mt], b[nt][0], b[nt][1]);
                }
            }
        }
        __syncthreads();

        if (q + 2 < 4) {
            const char* src = (const char*)g_wimg + (size_t)(q + 2)*32768
                            + (size_t)tid*16;
            uint32_t dst = wbase + tid*16;
#pragma unroll
            for (int i = 0; i < 4; i++) CP_ASYNC16(dst + i*8192, src + i*8192);
            CP_COMMIT();
        }
    }

    // ---- Epilogue: bias + sigmoid, both halves, from register fragments ----
    {
        const float* bias_s = (const float*)(sm + OFF_BIAS);
        float* uout = out + UOFF;
        const int qr = lane >> 2, cq = (lane & 3) * 2;
#pragma unroll
        for (int mt = 0; mt < 2; mt++) {
            size_t row0 = T0 + (size_t)(mg*32 + mt*16 + qr);
#pragma unroll
            for (int nt = 0; nt < 8; nt++) {
                const float* d = &acc[(mt*8 + nt)*4];
                int np = nt >> 1;
                int col = (np < 2 ? ng*32 + np*16 : 128 + ng*32 + (np-2)*16)
                        + (nt & 1)*8 + cq;
                float b0 = bias_s[col], b1 = bias_s[col+1];
                float2 v0, v1;
                v0.x = 1.0f / (1.0f + __expf(-(d[0] + b0)));
                v0.y = 1.0f / (1.0f + __expf(-(d[1] + b1)));
                v1.x = 1.0f / (1.0f + __expf(-(d[2] + b0)));
                v1.y = 1.0f / (1.0f + __expf(-(d[3] + b1)));
                *(float2*)(uout + row0*NB + col)     = v0;
                *(float2*)(uout + (row0+8)*NB + col) = v1;
            }
        }
    }
}

extern "C" void kernel_launch(void* const* d_in, const int* in_sizes, int n_in,
                              void* d_out, int out_size) {
    const float* x         = (const float*)d_in[0];
    const float* amp_w     = (const float*)d_in[1];
    const float* amp_b     = (const float*)d_in[2];
    const float* phase_w   = (const float*)d_in[3];
    const float* phase_b   = (const float*)d_in[4];
    const float* in_proj_w = (const float*)d_in[5];
    const float* in_proj_b = (const float*)d_in[6];
    const float* out_proj_w= (const float*)d_in[7];
    const float* out_proj_b= (const float*)d_in[8];
    const float* meas_w    = (const float*)d_in[9];
    const float* meas_b    = (const float*)d_in[10];
    const float* unc_w     = (const float*)d_in[11];
    const float* unc_b     = (const float*)d_in[12];
    float* out = (float*)d_out;

    cudaFuncSetAttribute(kCm, cudaFuncAttributeMaxDynamicSharedMemorySize, SMEM_TOT);

    kTW<<<256, 256>>>(unc_w);
    kTA<<<32, 256>>>(amp_w, phase_w);
    kA<<<512, 256>>>(x, amp_b, phase_b);
    kB<<<1024, 128>>>(in_proj_w, in_proj_b, out_proj_w, out_proj_b);
    kCm<<<1024, 512, SMEM_TOT>>>(meas_w, meas_b, unc_b, out);
}

// round 15
// speedup vs baseline: 1.0001x; 1.0001x over previous
#include <cuda_runtime.h>
#include <cuda_bf16.h>
#include <cuda_fp16.h>
#include <math.h>
#include <cstdint>

// Problem constants
#define BB   128
#define SS   1024
#define DIN  1024
#define NQ   8
#define NB   256
#define NH   4
#define TOKN (BB*SS)           // 131072 tokens
#define UOFF ((size_t)TOKN*NB) // offset of uncertainty in d_out

// Scratch (device globals: allocation-free)
__device__ float g_real[TOKN*NQ];
__device__ float g_imag[TOKN*NQ];
__device__ float g_meas[TOKN*NQ];
// fp16 unc_w image for mma.sync (2-product split: only W_hi needed):
// slab k64 = 0..3, each 32 KB = [256 o][64 k] fp16, ldmatrix-swizzled (128B rows).
__device__ unsigned char g_wimg[4*32768];
// Packed (amp,phase) projection weights: g_wax[k*8+j] = (aw[j][k], pw[j][k])
__device__ unsigned long long g_wax[DIN*8];

// ---------- f32x2 packed-FMA helpers ----------
static __device__ __forceinline__ unsigned long long pk2(float lo, float hi) {
    unsigned long long r;
    asm("mov.b64 %0, {%1,%2};" : "=l"(r) : "f"(lo), "f"(hi));
    return r;
}
static __device__ __forceinline__ void upk2(unsigned long long v, float& lo, float& hi) {
    asm("mov.b64 {%0,%1}, %2;" : "=f"(lo), "=f"(hi) : "l"(v));
}
static __device__ __forceinline__ unsigned long long ffma2(unsigned long long a,
                                                           unsigned long long b,
                                                           unsigned long long c) {
    unsigned long long d;
    asm("fma.rn.f32x2 %0, %1, %2, %3;" : "=l"(d) : "l"(a), "l"(b), "l"(c));
    return d;
}
static __device__ __forceinline__ float ex2f(float x) {
    float r;
    asm("ex2.approx.f32 %0, %1;" : "=f"(r) : "f"(x));
    return r;
}

// ---------- mma.sync / cp.async helpers (base-target) ----------
static __device__ __forceinline__ uint32_t smem_u32(const void* p) {
    uint32_t a;
    asm("{ .reg .u64 t; cvta.to.shared.u64 t, %1; cvt.u32.u64 %0, t; }" : "=r"(a) : "l"(p));
    return a;
}
#define LDSM4(r, addr) \
    asm volatile("ldmatrix.sync.aligned.m8n8.x4.shared.b16 {%0,%1,%2,%3}, [%4];" \
        : "=r"((r)[0]), "=r"((r)[1]), "=r"((r)[2]), "=r"((r)[3]) : "r"(addr))
#define MMA16816H(d, a, b0v, b1v) \
    asm volatile("mma.sync.aligned.m16n8k16.row.col.f32.f16.f16.f32 " \
        "{%0,%1,%2,%3}, {%4,%5,%6,%7}, {%8,%9}, {%0,%1,%2,%3};" \
        : "+f"((d)[0]), "+f"((d)[1]), "+f"((d)[2]), "+f"((d)[3]) \
        : "r"((a)[0]), "r"((a)[1]), "r"((a)[2]), "r"((a)[3]), "r"(b0v), "r"(b1v))
#define CP_ASYNC16(dst, src) \
    asm volatile("cp.async.cg.shared.global [%0], [%1], 16;" :: "r"(dst), "l"(src))
#define CP_COMMIT() asm volatile("cp.async.commit_group;" ::: "memory")
#define CP_WAIT(n)  asm volatile("cp.async.wait_group %0;" :: "n"(n) : "memory")

// ---------- prep: unc_w -> fp16 slabs [256 o][64 k] ----------
__global__ void kTW(const float* __restrict__ unc_w) {
    int idx = blockIdx.x * blockDim.x + threadIdx.x;
    if (idx >= NB*NB) return;
    int o = idx >> 8, k = idx & 255;
    float w = unc_w[o*NB + k];
    int k64 = k >> 6, kk = k & 63;
    unsigned byte = (unsigned)(o*128 + kk*2);
    byte ^= (o & 7) << 4;                       // ldmatrix swizzle (128B rows)
    *(__half*)(g_wimg + (size_t)k64*32768 + byte) = __float2half_rn(w);
}

// ---------- prep: pack (amp,phase) projection weights ----------
__global__ void kTA(const float* __restrict__ aw, const float* __restrict__ pw) {
    int idx = blockIdx.x * blockDim.x + threadIdx.x;
    if (idx >= DIN*8) return;
    int k = idx >> 3, j = idx & 7;
    g_wax[k*8 + j] = pk2(aw[j*DIN + k], pw[j*DIN + k]);
}

// ---------- Stage A: coalesced smem-staged projections + activations ----------
#define KCH 32
__global__ void __launch_bounds__(256) kA(const float* __restrict__ x,
                                          const float* __restrict__ ab,
                                          const float* __restrict__ pb) {
    __shared__ float4 tile[2][2048];            // 2 x 32 KB
    __shared__ unsigned long long wch[2][256];  // 2 x 2 KB
    const int tid = threadIdx.x;
    const size_t T0 = (size_t)blockIdx.x * 256;
    const uint32_t sb_tile = smem_u32(&tile[0][0]);
    const uint32_t sb_w    = smem_u32(&wch[0][0]);

#pragma unroll
    for (int pc = 0; pc < 2; pc++) {
#pragma unroll
        for (int i = 0; i < 8; i++) {
            int idx = i*256 + tid;
            int t = idx >> 3, k4 = idx & 7;
            const char* src = (const char*)(x + (T0 + t)*DIN + pc*KCH) + k4*16;
            uint32_t dst = sb_tile + pc*32768 + t*128 + ((k4 ^ (t & 7)) * 16);
            CP_ASYNC16(dst, src);
        }
        if (tid < 128)
            CP_ASYNC16(sb_w + pc*2048 + tid*16,
                       (const char*)g_wax + pc*2048 + tid*16);
        CP_COMMIT();
    }

    unsigned long long acc[8];
#pragma unroll
    for (int j = 0; j < 8; j++) acc[j] = 0ull;

#pragma unroll 1
    for (int c = 0; c < 32; c++) {
        const int buf = c & 1;
        if (c < 31) { CP_WAIT(1); } else { CP_WAIT(0); }
        __syncthreads();

        float4 xr[8];
#pragma unroll
        for (int k4 = 0; k4 < 8; k4++)
            xr[k4] = tile[buf][tid*8 + (k4 ^ (tid & 7))];

        const unsigned long long* wj = wch[buf];
#pragma unroll
        for (int kk = 0; kk < 32; kk++) {
            float xv = ((const float*)&xr[kk >> 2])[kk & 3];
            unsigned long long xp = pk2(xv, xv);
            const ulonglong2* wp = (const ulonglong2*)(wj + kk*8);
            ulonglong2 w01 = wp[0], w23 = wp[1], w45 = wp[2], w67 = wp[3];
            acc[0] = ffma2(xp, w01.x, acc[0]);
            acc[1] = ffma2(xp, w01.y, acc[1]);
            acc[2] = ffma2(xp, w23.x, acc[2]);
            acc[3] = ffma2(xp, w23.y, acc[3]);
            acc[4] = ffma2(xp, w45.x, acc[4]);
            acc[5] = ffma2(xp, w45.y, acc[5]);
            acc[6] = ffma2(xp, w67.x, acc[6]);
            acc[7] = ffma2(xp, w67.y, acc[7]);
        }
        __syncthreads();

        if (c + 2 < 32) {
#pragma unroll
            for (int i = 0; i < 8; i++) {
                int idx = i*256 + tid;
                int t = idx >> 3, k4 = idx & 7;
                const char* src = (const char*)(x + (T0 + t)*DIN + (c+2)*KCH) + k4*16;
                uint32_t dst = sb_tile + buf*32768 + t*128 + ((k4 ^ (t & 7)) * 16);
                CP_ASYNC16(dst, src);
            }
            if (tid < 128)
                CP_ASYNC16(sb_w + buf*2048 + tid*16,
                           (const char*)g_wax + (c+2)*2048 + tid*16);
            CP_COMMIT();
        }
    }

    float orr[8], oii[8];
#pragma unroll
    for (int j = 0; j < 8; j++) {
        float va, vp;
        upk2(acc[j], va, vp);
        float amp = tanhf(va + __ldg(ab + j));
        float ph  = 6.283185307179586f / (1.0f + expf(-(vp + __ldg(pb + j))));
        float s, cc;
        sincosf(ph, &s, &cc);
        orr[j] = amp * cc;
        oii[j] = amp * s;
    }
    float4* pr = (float4*)(g_real + (T0 + tid)*NQ);
    float4* pi = (float4*)(g_imag + (T0 + tid)*NQ);
    pr[0] = make_float4(orr[0], orr[1], orr[2], orr[3]);
    pr[1] = make_float4(orr[4], orr[5], orr[6], orr[7]);
    pi[0] = make_float4(oii[0], oii[1], oii[2], oii[3]);
    pi[1] = make_float4(oii[4], oii[5], oii[6], oii[7]);
}

// ---------- Stage B: dual MHA + out_proj + |.| (packed, ex2-based softmax) ----------
// q pre-scaled by (1/sqrt(Dh))*log2(e) so the score IS the ex2 argument.
__global__ void __launch_bounds__(128) kB(const float* __restrict__ ipw,
                                          const float* __restrict__ ipb,
                                          const float* __restrict__ opw,
                                          const float* __restrict__ opb) {
    __shared__ float4 ksv[128][4];
    __shared__ float4 vsv[128][4];
    __shared__ float s_ipw[24][8];
    __shared__ float s_ipb[24];
    __shared__ float s_opw[8][8];
    __shared__ float s_opb[8];

    const int l = threadIdx.x;
    const int n = blockIdx.x;

    if (l < 24) {
        s_ipb[l] = ipb[l];
#pragma unroll
        for (int e = 0; e < 8; e++) s_ipw[l][e] = ipw[l*8 + e];
    }
    if (l < 8) {
        s_opb[l] = opb[l];
#pragma unroll
        for (int j = 0; j < 8; j++) s_opw[l][j] = opw[l*8 + j];
    }

    const size_t base = ((size_t)l * SS + n) * NQ;
    float st[2][8];
    {
        float4 r0 = *(const float4*)(g_real + base);
        float4 r1 = *(const float4*)(g_real + base + 4);
        float4 i0 = *(const float4*)(g_imag + base);
        float4 i1 = *(const float4*)(g_imag + base + 4);
        st[0][0]=r0.x; st[0][1]=r0.y; st[0][2]=r0.z; st[0][3]=r0.w;
        st[0][4]=r1.x; st[0][5]=r1.y; st[0][6]=r1.z; st[0][7]=r1.w;
        st[1][0]=i0.x; st[1][1]=i0.y; st[1][2]=i0.z; st[1][3]=i0.w;
        st[1][4]=i1.x; st[1][5]=i1.y; st[1][6]=i1.z; st[1][7]=i1.w;
    }
    __syncthreads();

    float qb[2][8];
    float kv0[8], kv1[8], vv0[8], vv1[8];
#pragma unroll
    for (int p = 0; p < 2; p++) {
#pragma unroll
        for (int j = 0; j < 8; j++) {
            float q = s_ipb[j], k = s_ipb[8+j], v = s_ipb[16+j];
#pragma unroll
            for (int e = 0; e < 8; e++) {
                q = fmaf(s_ipw[j][e],    st[p][e], q);
                k = fmaf(s_ipw[8+j][e],  st[p][e], k);
                v = fmaf(s_ipw[16+j][e], st[p][e], v);
            }
            qb[p][j] = q;
            if (p == 0) { kv0[j] = k; vv0[j] = v; }
            else        { kv1[j] = k; vv1[j] = v; }
        }
    }
#pragma unroll
    for (int h = 0; h < NH; h++) {
        ksv[l][h] = make_float4(kv0[2*h], kv1[2*h], kv0[2*h+1], kv1[2*h+1]);
        vsv[l][h] = make_float4(vv0[2*h], vv1[2*h], vv0[2*h+1], vv1[2*h+1]);
    }
    __syncthreads();

    // packed q per head, pre-scaled by (1/sqrt(2))*log2(e)
    const float SC = 0.70710678118654752f * 1.4426950408889634f;
    unsigned long long qp0[NH], qp1[NH];
#pragma unroll
    for (int h = 0; h < NH; h++) {
        qp0[h] = pk2(qb[0][2*h]*SC,   qb[1][2*h]*SC);
        qp1[h] = pk2(qb[0][2*h+1]*SC, qb[1][2*h+1]*SC);
    }
    const unsigned long long one2 = pk2(1.0f, 1.0f);

    unsigned long long den2[NH], o02[NH], o12[NH];
#pragma unroll
    for (int h = 0; h < NH; h++) { den2[h] = 0ull; o02[h] = 0ull; o12[h] = 0ull; }

    for (int m = 0; m < 128; m++) {
        const ulonglong2* kr = (const ulonglong2*)&ksv[m][0];
        const ulonglong2* vr = (const ulonglong2*)&vsv[m][0];
#pragma unroll
        for (int h = 0; h < NH; h++) {
            ulonglong2 kk = kr[h];
            ulonglong2 vv = vr[h];
            unsigned long long s2 = ffma2(qp1[h], kk.y, 0ull);
            s2 = ffma2(qp0[h], kk.x, s2);
            float s0, s1;
            upk2(s2, s0, s1);
            unsigned long long e2 = pk2(ex2f(s0), ex2f(s1));
            den2[h] = ffma2(e2, one2, den2[h]);
            o02[h]  = ffma2(e2, vv.x, o02[h]);
            o12[h]  = ffma2(e2, vv.y, o12[h]);
        }
    }

    float ent[2][8];
#pragma unroll
    for (int h = 0; h < NH; h++) {
        float d0, d1, a0, a1, b0, b1;
        upk2(den2[h], d0, d1);
        upk2(o02[h], a0, a1);
        upk2(o12[h], b0, b1);
        float i0 = __fdividef(1.0f, d0), i1 = __fdividef(1.0f, d1);
        ent[0][2*h]   = a0 * i0;  ent[1][2*h]   = a1 * i1;
        ent[0][2*h+1] = b0 * i0;  ent[1][2*h+1] = b1 * i1;
    }

    float out[8];
#pragma unroll
    for (int e = 0; e < 8; e++) {
        float er = s_opb[e], ei = s_opb[e];
#pragma unroll
        for (int j = 0; j < 8; j++) {
            er = fmaf(s_opw[e][j], ent[0][j], er);
            ei = fmaf(s_opw[e][j], ent[1][j], ei);
        }
        out[e] = sqrtf(er*er + ei*ei);
    }
    float4* pm = (float4*)(g_meas + base);
    pm[0] = make_float4(out[0], out[1], out[2], out[3]);
    pm[1] = make_float4(out[4], out[5], out[6], out[7]);
}

// ---------- Stage C: fused compressed + fp16 2-product mma.sync GEMM ----------
// CTA = 128 tokens x 256 outputs, 512 threads. A = Ah + Al (fp16 pair, ~22
// bits of the fp32 compressed value); W = Wh (fp16). out = Ah*Wh + Al*Wh.
// 4 W slabs [256 o][64 k], cp.async double-buffered, prefetch 2 ahead.
#define OFF_MEAS 0
#define OFF_BIAS 4096
#define OFF_A    5120
#define OFF_ALO  (OFF_A + 65536)
#define OFF_W0   (OFF_ALO + 65536)
#define OFF_W1   (OFF_W0 + 32768)
#define SMEM_TOT (OFF_W1 + 32768)   // 201728 bytes

__global__ void __launch_bounds__(512, 1) kCm(const float* __restrict__ meas_w,
                                              const float* __restrict__ meas_b,
                                              const float* __restrict__ unc_b,
                                              float* __restrict__ out) {
    extern __shared__ unsigned char sm[];
    const uint32_t sb = smem_u32(sm);
    const int tid = threadIdx.x, wid = tid >> 5, lane = tid & 31;
    const size_t T0 = (size_t)blockIdx.x * 128;

    // Prologue: prefetch W slabs 0/1 (overlaps phase 1).
    {
        const char* src0 = (const char*)g_wimg + (size_t)tid*16;
        uint32_t d0 = sb + OFF_W0 + tid*16;
        uint32_t d1 = sb + OFF_W1 + tid*16;
#pragma unroll
        for (int i = 0; i < 4; i++) CP_ASYNC16(d0 + i*8192, src0 + i*8192);
        CP_COMMIT();
#pragma unroll
        for (int i = 0; i < 4; i++) CP_ASYNC16(d1 + i*8192, src0 + 32768 + i*8192);
        CP_COMMIT();
    }

    if (tid < 256) {
        ((float4*)(sm + OFF_MEAS))[tid] = __ldg((const float4*)(g_meas + T0*NQ) + tid);
        ((float*)(sm + OFF_BIAS))[tid] = __ldg(unc_b + tid);
    }
    __syncthreads();

    // ---- Phase 1: compressed + fp16 split into swizzled A tiles ----
    {
        const int o  = tid & 255;
        const int th = tid >> 8;
        float4 w0 = __ldg((const float4*)(meas_w + o*NQ));
        float4 w1 = __ldg((const float4*)(meas_w + o*NQ) + 1);
        float bb  = __ldg(meas_b + o);
        float* orow = out + T0*NB + o;
        const int tbase = th*64;
#pragma unroll 4
        for (int tt = 0; tt < 64; tt++) {
            const int t = tbase + tt;
            const float4* mm = (const float4*)(sm + OFF_MEAS + t*32);
            float4 m0 = mm[0], m1 = mm[1];
            float cc = bb;
            cc = fmaf(w0.x, m0.x, cc); cc = fmaf(w0.y, m0.y, cc);
            cc = fmaf(w0.z, m0.z, cc); cc = fmaf(w0.w, m0.w, cc);
            cc = fmaf(w1.x, m1.x, cc); cc = fmaf(w1.y, m1.y, cc);
            cc = fmaf(w1.z, m1.z, cc); cc = fmaf(w1.w, m1.w, cc);
            orow[(size_t)t*NB] = cc;
            __half hi = __float2half_rn(cc);
            __half lo = __float2half_rn(cc - __half2float(hi));
            unsigned byte = (unsigned)(t*512 + o*2);
            byte ^= (t & 7) << 4;                 // ldmatrix swizzle (512B rows)
            *(__half*)(sm + OFF_A   + byte) = hi;
            *(__half*)(sm + OFF_ALO + byte) = lo;
        }
    }

    // ---- Phase 2: 4-slab pipelined loop, both output halves accumulated ----
    const int mg = wid & 3;    // token group: rows mg*32..+32
    const int ng = wid >> 2;   // 32-col group within each 128-col half
    const unsigned a_m   = (unsigned)(mg*32 + (lane & 15));
    const unsigned a_k8  = (unsigned)((lane >> 4) << 3);
    const unsigned b_lrow = (unsigned)((lane & 7) + ((lane >> 4) << 3));
    const unsigned b_k8  = (unsigned)(((lane >> 3) & 1) << 3);

    float acc[64];
#pragma unroll
    for (int i = 0; i < 64; i++) acc[i] = 0.f;

#pragma unroll 1
    for (int q = 0; q < 4; q++) {
        const uint32_t wbase = sb + ((q & 1) ? OFF_W1 : OFF_W0);

        if (q < 3) { CP_WAIT(1); } else { CP_WAIT(0); }
        __syncthreads();

#pragma unroll
        for (int s = 0; s < 4; s++) {
            uint32_t ah[2][4], al[2][4], b[8][2];
#pragma unroll
            for (int mt = 0; mt < 2; mt++) {
                unsigned m = a_m + mt*16;
                unsigned k = (unsigned)(q*64 + s*16) + a_k8;
                unsigned byte = (m*512 + k*2) ^ ((m & 7) << 4);
                LDSM4(ah[mt], sb + OFF_A   + byte);
                LDSM4(al[mt], sb + OFF_ALO + byte);
            }
#pragma unroll
            for (int np = 0; np < 4; np++) {
                unsigned row = (np < 2 ? (unsigned)(ng*32 + np*16)
                                       : (unsigned)(128 + ng*32 + (np-2)*16)) + b_lrow;
                unsigned kin = (unsigned)(s*16) + b_k8;
                unsigned byte = (row*128 + kin*2) ^ ((row & 7) << 4);
                uint32_t r[4];
                LDSM4(r, wbase + byte);
                b[np*2][0]   = r[0];  b[np*2][1]   = r[1];
                b[np*2+1][0] = r[2];  b[np*2+1][1] = r[3];
            }
#pragma unroll
            for (int mt = 0; mt < 2; mt++) {
#pragma unroll
                for (int nt = 0; nt < 8; nt++) {
                    float* d = &acc[(mt*8 + nt)*4];
                    MMA16816H(d, ah[mt], b[nt][0], b[nt][1]);
                    MMA16816H(d, al[mt], b[nt][0], b[nt][1]);
                }
            }
        }
        __syncthreads();

        if (q + 2 < 4) {
            const char* src = (const char*)g_wimg + (size_t)(q + 2)*32768
                            + (size_t)tid*16;
            uint32_t dst = wbase + tid*16;
#pragma unroll
            for (int i = 0; i < 4; i++) CP_ASYNC16(dst + i*8192, src + i*8192);
            CP_COMMIT();
        }
    }

    // ---- Epilogue: bias + sigmoid, both halves, from register fragments ----
    {
        const float* bias_s = (const float*)(sm + OFF_BIAS);
        float* uout = out + UOFF;
        const int qr = lane >> 2, cq = (lane & 3) * 2;
#pragma unroll
        for (int mt = 0; mt < 2; mt++) {
            size_t row0 = T0 + (size_t)(mg*32 + mt*16 + qr);
#pragma unroll
            for (int nt = 0; nt < 8; nt++) {
                const float* d = &acc[(mt*8 + nt)*4];
                int np = nt >> 1;
                int col = (np < 2 ? ng*32 + np*16 : 128 + ng*32 + (np-2)*16)
                        + (nt & 1)*8 + cq;
                float b0 = bias_s[col], b1 = bias_s[col+1];
                float2 v0, v1;
                v0.x = 1.0f / (1.0f + __expf(-(d[0] + b0)));
                v0.y = 1.0f / (1.0f + __expf(-(d[1] + b1)));
                v1.x = 1.0f / (1.0f + __expf(-(d[2] + b0)));
                v1.y = 1.0f / (1.0f + __expf(-(d[3] + b1)));
                *(float2*)(uout + row0*NB + col)     = v0;
                *(float2*)(uout + (row0+8)*NB + col) = v1;
            }
        }
    }
}

extern "C" void kernel_launch(void* const* d_in, const int* in_sizes, int n_in,
                              void* d_out, int out_size) {
    const float* x         = (const float*)d_in[0];
    const float* amp_w     = (const float*)d_in[1];
    const float* amp_b     = (const float*)d_in[2];
    const float* phase_w   = (const float*)d_in[3];
    const float* phase_b   = (const float*)d_in[4];
    const float* in_proj_w = (const float*)d_in[5];
    const float* in_proj_b = (const float*)d_in[6];
    const float* out_proj_w= (const float*)d_in[7];
    const float* out_proj_b= (const float*)d_in[8];
    const float* meas_w    = (const float*)d_in[9];
    const float* meas_b    = (const float*)d_in[10];
    const float* unc_w     = (const float*)d_in[11];
    const float* unc_b     = (const float*)d_in[12];
    float* out = (float*)d_out;

    cudaFuncSetAttribute(kCm, cudaFuncAttributeMaxDynamicSharedMemorySize, SMEM_TOT);

    kTW<<<256, 256>>>(unc_w);
    kTA<<<32, 256>>>(amp_w, phase_w);
    kA<<<512, 256>>>(x, amp_b, phase_b);
    kB<<<1024, 128>>>(in_proj_w, in_proj_b, out_proj_w, out_proj_b);
    kCm<<<1024, 512, SMEM_TOT>>>(meas_w, meas_b, unc_b, out);
}

// round 16
// speedup vs baseline: 1.0011x; 1.0010x over previous
#include <cuda_runtime.h>
#include <cuda_bf16.h>
#include <cuda_fp16.h>
#include <math.h>
#include <cstdint>

// Problem constants
#define BB   128
#define SS   1024
#define DIN  1024
#define NQ   8
#define NB   256
#define NH   4
#define TOKN (BB*SS)           // 131072 tokens
#define UOFF ((size_t)TOKN*NB) // offset of uncertainty in d_out

// Scratch (device globals: allocation-free)
__device__ float g_real[TOKN*NQ];
__device__ float g_imag[TOKN*NQ];
__device__ float g_meas[TOKN*NQ];
// fp16 unc_w image for mma.sync (2-product split: only W_hi needed):
// slab k64 = 0..3, each 32 KB = [256 o][64 k] fp16, ldmatrix-swizzled (128B rows).
__device__ unsigned char g_wimg[4*32768];
// Packed (amp,phase) projection weights: g_wax[k*8+j] = (aw[j][k], pw[j][k])
__device__ unsigned long long g_wax[DIN*8];

// ---------- f32x2 packed-FMA helpers ----------
static __device__ __forceinline__ unsigned long long pk2(float lo, float hi) {
    unsigned long long r;
    asm("mov.b64 %0, {%1,%2};" : "=l"(r) : "f"(lo), "f"(hi));
    return r;
}
static __device__ __forceinline__ void upk2(unsigned long long v, float& lo, float& hi) {
    asm("mov.b64 {%0,%1}, %2;" : "=f"(lo), "=f"(hi) : "l"(v));
}
static __device__ __forceinline__ unsigned long long ffma2(unsigned long long a,
                                                           unsigned long long b,
                                                           unsigned long long c) {
    unsigned long long d;
    asm("fma.rn.f32x2 %0, %1, %2, %3;" : "=l"(d) : "l"(a), "l"(b), "l"(c));
    return d;
}
static __device__ __forceinline__ float ex2f(float x) {
    float r;
    asm("ex2.approx.f32 %0, %1;" : "=f"(r) : "f"(x));
    return r;
}

// ---------- mma.sync / cp.async helpers (base-target) ----------
static __device__ __forceinline__ uint32_t smem_u32(const void* p) {
    uint32_t a;
    asm("{ .reg .u64 t; cvta.to.shared.u64 t, %1; cvt.u32.u64 %0, t; }" : "=r"(a) : "l"(p));
    return a;
}
#define LDSM4(r, addr) \
    asm volatile("ldmatrix.sync.aligned.m8n8.x4.shared.b16 {%0,%1,%2,%3}, [%4];" \
        : "=r"((r)[0]), "=r"((r)[1]), "=r"((r)[2]), "=r"((r)[3]) : "r"(addr))
#define MMA16816H(d, a, b0v, b1v) \
    asm volatile("mma.sync.aligned.m16n8k16.row.col.f32.f16.f16.f32 " \
        "{%0,%1,%2,%3}, {%4,%5,%6,%7}, {%8,%9}, {%0,%1,%2,%3};" \
        : "+f"((d)[0]), "+f"((d)[1]), "+f"((d)[2]), "+f"((d)[3]) \
        : "r"((a)[0]), "r"((a)[1]), "r"((a)[2]), "r"((a)[3]), "r"(b0v), "r"(b1v))
#define CP_ASYNC16(dst, src) \
    asm volatile("cp.async.cg.shared.global [%0], [%1], 16;" :: "r"(dst), "l"(src))
#define CP_COMMIT() asm volatile("cp.async.commit_group;" ::: "memory")
#define CP_WAIT(n)  asm volatile("cp.async.wait_group %0;" :: "n"(n) : "memory")

// ---------- prep: unc_w -> fp16 slabs [256 o][64 k] ----------
__global__ void kTW(const float* __restrict__ unc_w) {
    int idx = blockIdx.x * blockDim.x + threadIdx.x;
    if (idx >= NB*NB) return;
    int o = idx >> 8, k = idx & 255;
    float w = unc_w[o*NB + k];
    int k64 = k >> 6, kk = k & 63;
    unsigned byte = (unsigned)(o*128 + kk*2);
    byte ^= (o & 7) << 4;                       // ldmatrix swizzle (128B rows)
    *(__half*)(g_wimg + (size_t)k64*32768 + byte) = __float2half_rn(w);
}

// ---------- prep: pack (amp,phase) projection weights ----------
__global__ void kTA(const float* __restrict__ aw, const float* __restrict__ pw) {
    int idx = blockIdx.x * blockDim.x + threadIdx.x;
    if (idx >= DIN*8) return;
    int k = idx >> 3, j = idx & 7;
    g_wax[k*8 + j] = pk2(aw[j*DIN + k], pw[j*DIN + k]);
}

// ---------- Stage A: coalesced smem-staged projections + activations ----------
#define KCH 32
__global__ void __launch_bounds__(256) kA(const float* __restrict__ x,
                                          const float* __restrict__ ab,
                                          const float* __restrict__ pb) {
    __shared__ float4 tile[2][2048];            // 2 x 32 KB
    __shared__ unsigned long long wch[2][256];  // 2 x 2 KB
    const int tid = threadIdx.x;
    const size_t T0 = (size_t)blockIdx.x * 256;
    const uint32_t sb_tile = smem_u32(&tile[0][0]);
    const uint32_t sb_w    = smem_u32(&wch[0][0]);

#pragma unroll
    for (int pc = 0; pc < 2; pc++) {
#pragma unroll
        for (int i = 0; i < 8; i++) {
            int idx = i*256 + tid;
            int t = idx >> 3, k4 = idx & 7;
            const char* src = (const char*)(x + (T0 + t)*DIN + pc*KCH) + k4*16;
            uint32_t dst = sb_tile + pc*32768 + t*128 + ((k4 ^ (t & 7)) * 16);
            CP_ASYNC16(dst, src);
        }
        if (tid < 128)
            CP_ASYNC16(sb_w + pc*2048 + tid*16,
                       (const char*)g_wax + pc*2048 + tid*16);
        CP_COMMIT();
    }

    unsigned long long acc[8];
#pragma unroll
    for (int j = 0; j < 8; j++) acc[j] = 0ull;

#pragma unroll 1
    for (int c = 0; c < 32; c++) {
        const int buf = c & 1;
        if (c < 31) { CP_WAIT(1); } else { CP_WAIT(0); }
        __syncthreads();

        float4 xr[8];
#pragma unroll
        for (int k4 = 0; k4 < 8; k4++)
            xr[k4] = tile[buf][tid*8 + (k4 ^ (tid & 7))];

        const unsigned long long* wj = wch[buf];
#pragma unroll
        for (int kk = 0; kk < 32; kk++) {
            float xv = ((const float*)&xr[kk >> 2])[kk & 3];
            unsigned long long xp = pk2(xv, xv);
            const ulonglong2* wp = (const ulonglong2*)(wj + kk*8);
            ulonglong2 w01 = wp[0], w23 = wp[1], w45 = wp[2], w67 = wp[3];
            acc[0] = ffma2(xp, w01.x, acc[0]);
            acc[1] = ffma2(xp, w01.y, acc[1]);
            acc[2] = ffma2(xp, w23.x, acc[2]);
            acc[3] = ffma2(xp, w23.y, acc[3]);
            acc[4] = ffma2(xp, w45.x, acc[4]);
            acc[5] = ffma2(xp, w45.y, acc[5]);
            acc[6] = ffma2(xp, w67.x, acc[6]);
            acc[7] = ffma2(xp, w67.y, acc[7]);
        }
        __syncthreads();

        if (c + 2 < 32) {
#pragma unroll
            for (int i = 0; i < 8; i++) {
                int idx = i*256 + tid;
                int t = idx >> 3, k4 = idx & 7;
                const char* src = (const char*)(x + (T0 + t)*DIN + (c+2)*KCH) + k4*16;
                uint32_t dst = sb_tile + buf*32768 + t*128 + ((k4 ^ (t & 7)) * 16);
                CP_ASYNC16(dst, src);
            }
            if (tid < 128)
                CP_ASYNC16(sb_w + buf*2048 + tid*16,
                           (const char*)g_wax + (c+2)*2048 + tid*16);
            CP_COMMIT();
        }
    }

    float orr[8], oii[8];
#pragma unroll
    for (int j = 0; j < 8; j++) {
        float va, vp;
        upk2(acc[j], va, vp);
        float amp = tanhf(va + __ldg(ab + j));
        float ph  = 6.283185307179586f / (1.0f + expf(-(vp + __ldg(pb + j))));
        float s, cc;
        sincosf(ph, &s, &cc);
        orr[j] = amp * cc;
        oii[j] = amp * s;
    }
    float4* pr = (float4*)(g_real + (T0 + tid)*NQ);
    float4* pi = (float4*)(g_imag + (T0 + tid)*NQ);
    pr[0] = make_float4(orr[0], orr[1], orr[2], orr[3]);
    pr[1] = make_float4(orr[4], orr[5], orr[6], orr[7]);
    pi[0] = make_float4(oii[0], oii[1], oii[2], oii[3]);
    pi[1] = make_float4(oii[4], oii[5], oii[6], oii[7]);
}

// ---------- Stage B: dual MHA + out_proj + |.| (packed, ex2-based softmax) ----------
// q pre-scaled by (1/sqrt(Dh))*log2(e) so the score IS the ex2 argument.
__global__ void __launch_bounds__(128) kB(const float* __restrict__ ipw,
                                          const float* __restrict__ ipb,
                                          const float* __restrict__ opw,
                                          const float* __restrict__ opb) {
    __shared__ float4 ksv[128][4];
    __shared__ float4 vsv[128][4];
    __shared__ float s_ipw[24][8];
    __shared__ float s_ipb[24];
    __shared__ float s_opw[8][8];
    __shared__ float s_opb[8];

    const int l = threadIdx.x;
    const int n = blockIdx.x;

    if (l < 24) {
        s_ipb[l] = ipb[l];
#pragma unroll
        for (int e = 0; e < 8; e++) s_ipw[l][e] = ipw[l*8 + e];
    }
    if (l < 8) {
        s_opb[l] = opb[l];
#pragma unroll
        for (int j = 0; j < 8; j++) s_opw[l][j] = opw[l*8 + j];
    }

    const size_t base = ((size_t)l * SS + n) * NQ;
    float st[2][8];
    {
        float4 r0 = *(const float4*)(g_real + base);
        float4 r1 = *(const float4*)(g_real + base + 4);
        float4 i0 = *(const float4*)(g_imag + base);
        float4 i1 = *(const float4*)(g_imag + base + 4);
        st[0][0]=r0.x; st[0][1]=r0.y; st[0][2]=r0.z; st[0][3]=r0.w;
        st[0][4]=r1.x; st[0][5]=r1.y; st[0][6]=r1.z; st[0][7]=r1.w;
        st[1][0]=i0.x; st[1][1]=i0.y; st[1][2]=i0.z; st[1][3]=i0.w;
        st[1][4]=i1.x; st[1][5]=i1.y; st[1][6]=i1.z; st[1][7]=i1.w;
    }
    __syncthreads();

    float qb[2][8];
    float kv0[8], kv1[8], vv0[8], vv1[8];
#pragma unroll
    for (int p = 0; p < 2; p++) {
#pragma unroll
        for (int j = 0; j < 8; j++) {
            float q = s_ipb[j], k = s_ipb[8+j], v = s_ipb[16+j];
#pragma unroll
            for (int e = 0; e < 8; e++) {
                q = fmaf(s_ipw[j][e],    st[p][e], q);
                k = fmaf(s_ipw[8+j][e],  st[p][e], k);
                v = fmaf(s_ipw[16+j][e], st[p][e], v);
            }
            qb[p][j] = q;
            if (p == 0) { kv0[j] = k; vv0[j] = v; }
            else        { kv1[j] = k; vv1[j] = v; }
        }
    }
#pragma unroll
    for (int h = 0; h < NH; h++) {
        ksv[l][h] = make_float4(kv0[2*h], kv1[2*h], kv0[2*h+1], kv1[2*h+1]);
        vsv[l][h] = make_float4(vv0[2*h], vv1[2*h], vv0[2*h+1], vv1[2*h+1]);
    }
    __syncthreads();

    // packed q per head, pre-scaled by (1/sqrt(2))*log2(e)
    const float SC = 0.70710678118654752f * 1.4426950408889634f;
    unsigned long long qp0[NH], qp1[NH];
#pragma unroll
    for (int h = 0; h < NH; h++) {
        qp0[h] = pk2(qb[0][2*h]*SC,   qb[1][2*h]*SC);
        qp1[h] = pk2(qb[0][2*h+1]*SC, qb[1][2*h+1]*SC);
    }
    const unsigned long long one2 = pk2(1.0f, 1.0f);

    unsigned long long den2[NH], o02[NH], o12[NH];
#pragma unroll
    for (int h = 0; h < NH; h++) { den2[h] = 0ull; o02[h] = 0ull; o12[h] = 0ull; }

    for (int m = 0; m < 128; m++) {
        const ulonglong2* kr = (const ulonglong2*)&ksv[m][0];
        const ulonglong2* vr = (const ulonglong2*)&vsv[m][0];
#pragma unroll
        for (int h = 0; h < NH; h++) {
            ulonglong2 kk = kr[h];
            ulonglong2 vv = vr[h];
            unsigned long long s2 = ffma2(qp1[h], kk.y, 0ull);
            s2 = ffma2(qp0[h], kk.x, s2);
            float s0, s1;
            upk2(s2, s0, s1);
            unsigned long long e2 = pk2(ex2f(s0), ex2f(s1));
            den2[h] = ffma2(e2, one2, den2[h]);
            o02[h]  = ffma2(e2, vv.x, o02[h]);
            o12[h]  = ffma2(e2, vv.y, o12[h]);
        }
    }

    float ent[2][8];
#pragma unroll
    for (int h = 0; h < NH; h++) {
        float d0, d1, a0, a1, b0, b1;
        upk2(den2[h], d0, d1);
        upk2(o02[h], a0, a1);
        upk2(o12[h], b0, b1);
        float i0 = __fdividef(1.0f, d0), i1 = __fdividef(1.0f, d1);
        ent[0][2*h]   = a0 * i0;  ent[1][2*h]   = a1 * i1;
        ent[0][2*h+1] = b0 * i0;  ent[1][2*h+1] = b1 * i1;
    }

    float out[8];
#pragma unroll
    for (int e = 0; e < 8; e++) {
        float er = s_opb[e], ei = s_opb[e];
#pragma unroll
        for (int j = 0; j < 8; j++) {
            er = fmaf(s_opw[e][j], ent[0][j], er);
            ei = fmaf(s_opw[e][j], ent[1][j], ei);
        }
        out[e] = sqrtf(er*er + ei*ei);
    }
    float4* pm = (float4*)(g_meas + base);
    pm[0] = make_float4(out[0], out[1], out[2], out[3]);
    pm[1] = make_float4(out[4], out[5], out[6], out[7]);
}

// ---------- Stage C: fused compressed + fp16 2-product mma.sync GEMM ----------
// CTA = 128 tokens x 256 outputs, 512 threads. A = Ah + Al (fp16 pair, ~22
// bits of the fp32 compressed value); W = Wh (fp16). out = Ah*Wh + Al*Wh.
// 4 W slabs [256 o][64 k], cp.async double-buffered, prefetch 2 ahead.
#define OFF_MEAS 0
#define OFF_BIAS 4096
#define OFF_A    5120
#define OFF_ALO  (OFF_A + 65536)
#define OFF_W0   (OFF_ALO + 65536)
#define OFF_W1   (OFF_W0 + 32768)
#define SMEM_TOT (OFF_W1 + 32768)   // 201728 bytes

__global__ void __launch_bounds__(512, 1) kCm(const float* __restrict__ meas_w,
                                              const float* __restrict__ meas_b,
                                              const float* __restrict__ unc_b,
                                              float* __restrict__ out) {
    extern __shared__ unsigned char sm[];
    const uint32_t sb = smem_u32(sm);
    const int tid = threadIdx.x, wid = tid >> 5, lane = tid & 31;
    const size_t T0 = (size_t)blockIdx.x * 128;

    // Prologue: prefetch W slabs 0/1 (overlaps phase 1).
    {
        const char* src0 = (const char*)g_wimg + (size_t)tid*16;
        uint32_t d0 = sb + OFF_W0 + tid*16;
        uint32_t d1 = sb + OFF_W1 + tid*16;
#pragma unroll
        for (int i = 0; i < 4; i++) CP_ASYNC16(d0 + i*8192, src0 + i*8192);
        CP_COMMIT();
#pragma unroll
        for (int i = 0; i < 4; i++) CP_ASYNC16(d1 + i*8192, src0 + 32768 + i*8192);
        CP_COMMIT();
    }

    if (tid < 256) {
        ((float4*)(sm + OFF_MEAS))[tid] = __ldg((const float4*)(g_meas + T0*NQ) + tid);
        ((float*)(sm + OFF_BIAS))[tid] = __ldg(unc_b + tid);
    }
    __syncthreads();

    // ---- Phase 1: compressed + fp16 split into swizzled A tiles ----
    {
        const int o  = tid & 255;
        const int th = tid >> 8;
        float4 w0 = __ldg((const float4*)(meas_w + o*NQ));
        float4 w1 = __ldg((const float4*)(meas_w + o*NQ) + 1);
        float bb  = __ldg(meas_b + o);
        float* orow = out + T0*NB + o;
        const int tbase = th*64;
#pragma unroll 4
        for (int tt = 0; tt < 64; tt++) {
            const int t = tbase + tt;
            const float4* mm = (const float4*)(sm + OFF_MEAS + t*32);
            float4 m0 = mm[0], m1 = mm[1];
            float cc = bb;
            cc = fmaf(w0.x, m0.x, cc); cc = fmaf(w0.y, m0.y, cc);
            cc = fmaf(w0.z, m0.z, cc); cc = fmaf(w0.w, m0.w, cc);
            cc = fmaf(w1.x, m1.x, cc); cc = fmaf(w1.y, m1.y, cc);
            cc = fmaf(w1.z, m1.z, cc); cc = fmaf(w1.w, m1.w, cc);
            orow[(size_t)t*NB] = cc;
            __half hi = __float2half_rn(cc);
            __half lo = __float2half_rn(cc - __half2float(hi));
            unsigned byte = (unsigned)(t*512 + o*2);
            byte ^= (t & 7) << 4;                 // ldmatrix swizzle (512B rows)
            *(__half*)(sm + OFF_A   + byte) = hi;
            *(__half*)(sm + OFF_ALO + byte) = lo;
        }
    }

    // ---- Phase 2: 4-slab pipelined loop, both output halves accumulated ----
    const int mg = wid & 3;    // token group: rows mg*32..+32
    const int ng = wid >> 2;   // 32-col group within each 128-col half
    const unsigned a_m   = (unsigned)(mg*32 + (lane & 15));
    const unsigned a_k8  = (unsigned)((lane >> 4) << 3);
    const unsigned b_lrow = (unsigned)((lane & 7) + ((lane >> 4) << 3));
    const unsigned b_k8  = (unsigned)(((lane >> 3) & 1) << 3);

    float acc[64];
#pragma unroll
    for (int i = 0; i < 64; i++) acc[i] = 0.f;

#pragma unroll 1
    for (int q = 0; q < 4; q++) {
        const uint32_t wbase = sb + ((q & 1) ? OFF_W1 : OFF_W0);

        if (q < 3) { CP_WAIT(1); } else { CP_WAIT(0); }
        __syncthreads();

#pragma unroll
        for (int s = 0; s < 4; s++) {
            uint32_t ah[2][4], al[2][4], b[8][2];
#pragma unroll
            for (int mt = 0; mt < 2; mt++) {
                unsigned m = a_m + mt*16;
                unsigned k = (unsigned)(q*64 + s*16) + a_k8;
                unsigned byte = (m*512 + k*2) ^ ((m & 7) << 4);
                LDSM4(ah[mt], sb + OFF_A   + byte);
                LDSM4(al[mt], sb + OFF_ALO + byte);
            }
#pragma unroll
            for (int np = 0; np < 4; np++) {
                unsigned row = (np < 2 ? (unsigned)(ng*32 + np*16)
                                       : (unsigned)(128 + ng*32 + (np-2)*16)) + b_lrow;
                unsigned kin = (unsigned)(s*16) + b_k8;
                unsigned byte = (row*128 + kin*2) ^ ((row & 7) << 4);
                uint32_t r[4];
                LDSM4(r, wbase + byte);
                b[np*2][0]   = r[0];  b[np*2][1]   = r[1];
                b[np*2+1][0] = r[2];  b[np*2+1][1] = r[3];
            }
#pragma unroll
            for (int mt = 0; mt < 2; mt++) {
#pragma unroll
                for (int nt = 0; nt < 8; nt++) {
                    float* d = &acc[(mt*8 + nt)*4];
                    MMA16816H(d, ah[mt], b[nt][0], b[nt][1]);
                    MMA16816H(d, al[mt], b[nt][0], b[nt][1]);
                }
            }
        }
        __syncthreads();

        if (q + 2 < 4) {
            const char* src = (const char*)g_wimg + (size_t)(q + 2)*32768
                            + (size_t)tid*16;
            uint32_t dst = wbase + tid*16;
#pragma unroll
            for (int i = 0; i < 4; i++) CP_ASYNC16(dst + i*8192, src + i*8192);
            CP_COMMIT();
        }
    }

    // ---- Epilogue: bias + sigmoid, both halves, from register fragments ----
    {
        const float* bias_s = (const float*)(sm + OFF_BIAS);
        float* uout = out + UOFF;
        const int qr = lane >> 2, cq = (lane & 3) * 2;
#pragma unroll
        for (int mt = 0; mt < 2; mt++) {
            size_t row0 = T0 + (size_t)(mg*32 + mt*16 + qr);
#pragma unroll
            for (int nt = 0; nt < 8; nt++) {
                const float* d = &acc[(mt*8 + nt)*4];
                int np = nt >> 1;
                int col = (np < 2 ? ng*32 + np*16 : 128 + ng*32 + (np-2)*16)
                        + (nt & 1)*8 + cq;
                float b0 = bias_s[col], b1 = bias_s[col+1];
                float2 v0, v1;
                v0.x = 1.0f / (1.0f + __expf(-(d[0] + b0)));
                v0.y = 1.0f / (1.0f + __expf(-(d[1] + b1)));
                v1.x = 1.0f / (1.0f + __expf(-(d[2] + b0)));
                v1.y = 1.0f / (1.0f + __expf(-(d[3] + b1)));
                *(float2*)(uout + row0*NB + col)     = v0;
                *(float2*)(uout + (row0+8)*NB + col) = v1;
            }
        }
    }
}

extern "C" void kernel_launch(void* const* d_in, const int* in_sizes, int n_in,
                              void* d_out, int out_size) {
    const float* x         = (const float*)d_in[0];
    const float* amp_w     = (const float*)d_in[1];
    const float* amp_b     = (const float*)d_in[2];
    const float* phase_w   = (const float*)d_in[3];
    const float* phase_b   = (const float*)d_in[4];
    const float* in_proj_w = (const float*)d_in[5];
    const float* in_proj_b = (const float*)d_in[6];
    const float* out_proj_w= (const float*)d_in[7];
    const float* out_proj_b= (const float*)d_in[8];
    const float* meas_w    = (const float*)d_in[9];
    const float* meas_b    = (const float*)d_in[10];
    const float* unc_w     = (const float*)d_in[11];
    const float* unc_b     = (const float*)d_in[12];
    float* out = (float*)d_out;

    cudaFuncSetAttribute(kCm, cudaFuncAttributeMaxDynamicSharedMemorySize, SMEM_TOT);

    kTW<<<256, 256>>>(unc_w);
    kTA<<<32, 256>>>(amp_w, phase_w);
    kA<<<512, 256>>>(x, amp_b, phase_b);
    kB<<<1024, 128>>>(in_proj_w, in_proj_b, out_proj_w, out_proj_b);
    kCm<<<1024, 512, SMEM_TOT>>>(meas_w, meas_b, unc_b, out);
}